// round 17
// baseline (speedup 1.0000x reference)
#include <cuda_runtime.h>
#include <cuda_fp16.h>
#include <math.h>

#define Nn 100000
#define Ee 800000
#define Dd 64
#define HC 128
#define SCB 512
#define NSCAN_BLOCKS ((Nn + SCB - 1) / SCB)   // 196

// ---------------- device scratch (static: no allocation allowed) -------------
__device__ int    g_is64;
__device__ int    g_deg[Nn];
__device__ int    g_rowptr[Nn];
__device__ int    g_cursor[Nn];
__device__ int    g_colsrc[Ee];
__device__ int    g_bsums[NSCAN_BLOCKS + 8];
__device__ __half g_xl[Nn * HC];   // 25.6 MB (fp16 storage)
__device__ __half g_xr[Nn * HC];   // 25.6 MB
__device__ float  g_x [Nn * Dd];   // 25.6 MB (inter-layer activations, fp32)

// ---------------- fp16 pack/unpack helpers -----------------------------------
__device__ __forceinline__ float4 ld_half4(const __half* p) {
    uint2 v = *(const uint2*)p;
    __half2 h0 = *(__half2*)&v.x;
    __half2 h1 = *(__half2*)&v.y;
    float2 f0 = __half22float2(h0);
    float2 f1 = __half22float2(h1);
    return make_float4(f0.x, f0.y, f1.x, f1.y);
}
__device__ __forceinline__ void st_half4(__half* p, float4 v) {
    __half2 h0 = __floats2half2_rn(v.x, v.y);
    __half2 h1 = __floats2half2_rn(v.z, v.w);
    uint2 o;
    o.x = *(unsigned*)&h0;
    o.y = *(unsigned*)&h1;
    *(uint2*)p = o;
}

// ---------------- edge dtype detection (int64 vs int32) ----------------------
__global__ void k_detect(const void* edges) {
    if (threadIdx.x == 0) {
        const int* p = (const int*)edges;
        int all0 = 1;
        #pragma unroll 1
        for (int i = 1; i < 128; i += 2) {
            if (p[i] != 0) { all0 = 0; break; }
        }
        g_is64 = all0;   // node ids < 2^31 -> high words all zero iff int64
    }
}

__device__ __forceinline__ int edge_at(const void* edges, int i) {
    if (g_is64) return (int)((const long long*)edges)[i];
    return ((const int*)edges)[i];
}

// ---------------- CSR build --------------------------------------------------
__global__ void k_zero_deg() {
    int i = blockIdx.x * blockDim.x + threadIdx.x;
    if (i < Nn) g_deg[i] = 0;
}

__global__ void k_count(const void* edges) {
    int i = blockIdx.x * blockDim.x + threadIdx.x;
    if (i >= Ee) return;
    int dst = edge_at(edges, Ee + i);
    atomicAdd(&g_deg[dst], 1);
}

__global__ void k_scan1() {
    __shared__ int sh[SCB];
    int i = blockIdx.x * SCB + threadIdx.x;
    sh[threadIdx.x] = (i < Nn) ? g_deg[i] : 0;
    __syncthreads();
    for (int s = SCB / 2; s > 0; s >>= 1) {
        if (threadIdx.x < s) sh[threadIdx.x] += sh[threadIdx.x + s];
        __syncthreads();
    }
    if (threadIdx.x == 0) g_bsums[blockIdx.x] = sh[0];
}

__global__ void k_scan2(int nb) {
    if (threadIdx.x == 0) {
        int acc = 0;
        for (int b = 0; b < nb; b++) { int v = g_bsums[b]; g_bsums[b] = acc; acc += v; }
    }
}

__global__ void k_scan3() {
    __shared__ int sh[SCB];
    int i = blockIdx.x * SCB + threadIdx.x;
    int v = (i < Nn) ? g_deg[i] : 0;
    sh[threadIdx.x] = v;
    __syncthreads();
    for (int s = 1; s < SCB; s <<= 1) {
        int t = (threadIdx.x >= s) ? sh[threadIdx.x - s] : 0;
        __syncthreads();
        sh[threadIdx.x] += t;
        __syncthreads();
    }
    if (i < Nn) {
        int excl = g_bsums[blockIdx.x] + sh[threadIdx.x] - v;  // exclusive prefix
        g_rowptr[i] = excl;
        g_cursor[i] = excl;
    }
}

__global__ void k_scatter(const void* edges) {
    int i = blockIdx.x * blockDim.x + threadIdx.x;
    if (i >= Ee) return;
    int src = edge_at(edges, i);
    int dst = edge_at(edges, Ee + i);
    int pos = atomicAdd(&g_cursor[dst], 1);
    g_colsrc[pos] = src;
}

// ---------------- GEMM: out[N,128] = x[N,64] @ W[64,128] + b  (fp16 out) -----
#define AP 132   // padded row length for transposed A tile

typedef unsigned long long u64;

__device__ __forceinline__ u64 packf2(float a, float b) {
    u64 d;
    asm("mov.b64 %0, {%1, %2};" : "=l"(d) : "f"(a), "f"(b));
    return d;
}
__device__ __forceinline__ void unpackf2(u64 v, float& lo, float& hi) {
    asm("mov.b64 {%0, %1}, %2;" : "=f"(lo), "=f"(hi) : "l"(v));
}
__device__ __forceinline__ void fma2(u64& acc, u64 a, u64 b) {
    asm("fma.rn.f32x2 %0, %1, %2, %0;" : "+l"(acc) : "l"(a), "l"(b));
}

__global__ __launch_bounds__(256, 2)
void k_gemm(const float* __restrict__ xext, int use_gx,
            const float* __restrict__ Wl, const float* __restrict__ Wr,
            const float* __restrict__ bl, const float* __restrict__ br) {
    extern __shared__ float smem[];
    float* As = smem;              // [64][AP]  (transposed: As[k][r])
    float* Bs = smem + 64 * AP;    // [64][128]

    const float* x = use_gx ? g_x : xext;
    const float* W = (blockIdx.y == 0) ? Wl : Wr;
    const float* bvec = (blockIdx.y == 0) ? bl : br;
    __half* out = (blockIdx.y == 0) ? g_xl : g_xr;

    int tid = threadIdx.x;
    int row0 = blockIdx.x * 128;

    for (int i = tid; i < 64 * 32; i += 256) {
        int k = i >> 5, c4 = (i & 31) * 4;
        float4 v = *(const float4*)(W + k * 128 + c4);
        *(float4*)(&Bs[k * 128 + c4]) = v;
    }
    for (int i = tid; i < 128 * 16; i += 256) {
        int r = i >> 4, k4 = (i & 15) * 4;
        int row = row0 + r;
        float4 v = make_float4(0.f, 0.f, 0.f, 0.f);
        if (row < Nn) v = *(const float4*)(x + (size_t)row * 64 + k4);
        As[(k4 + 0) * AP + r] = v.x;
        As[(k4 + 1) * AP + r] = v.y;
        As[(k4 + 2) * AP + r] = v.z;
        As[(k4 + 3) * AP + r] = v.w;
    }
    __syncthreads();

    int tx = tid & 15, ty = tid >> 4;
    int ra = ty * 4, rb = 64 + ty * 4;
    int ca = tx * 4, cb = 64 + tx * 4;

    u64 acc[8][4];
    #pragma unroll
    for (int i = 0; i < 8; i++)
        #pragma unroll
        for (int j = 0; j < 4; j++) acc[i][j] = 0ull;

    #pragma unroll 4
    for (int k = 0; k < 64; k++) {
        float a[8];
        *(float4*)(a)     = *(float4*)(&As[k * AP + ra]);
        *(float4*)(a + 4) = *(float4*)(&As[k * AP + rb]);
        u64 b2[4];
        float4 bva = *(float4*)(&Bs[k * 128 + ca]);
        float4 bvb = *(float4*)(&Bs[k * 128 + cb]);
        b2[0] = packf2(bva.x, bva.y);
        b2[1] = packf2(bva.z, bva.w);
        b2[2] = packf2(bvb.x, bvb.y);
        b2[3] = packf2(bvb.z, bvb.w);
        u64 pa[8];
        #pragma unroll
        for (int i = 0; i < 8; i++) pa[i] = packf2(a[i], a[i]);
        #pragma unroll
        for (int i = 0; i < 8; i++) {
            fma2(acc[i][0], pa[i], b2[0]);
            fma2(acc[i][1], pa[i], b2[1]);
            fma2(acc[i][2], pa[i], b2[2]);
            fma2(acc[i][3], pa[i], b2[3]);
        }
    }

    float bb[8];
    *(float4*)(bb)     = *(const float4*)(bvec + ca);
    *(float4*)(bb + 4) = *(const float4*)(bvec + cb);

    #pragma unroll
    for (int i = 0; i < 8; i++) {
        int rl = (i < 4) ? (ra + i) : (rb + i - 4);
        int row = row0 + rl;
        if (row >= Nn) continue;
        float c0, c1, c2, c3, c4x, c5, c6, c7;
        unpackf2(acc[i][0], c0, c1);
        unpackf2(acc[i][1], c2, c3);
        unpackf2(acc[i][2], c4x, c5);
        unpackf2(acc[i][3], c6, c7);
        float4 o1 = make_float4(c0 + bb[0], c1 + bb[1], c2 + bb[2], c3 + bb[3]);
        float4 o2 = make_float4(c4x + bb[4], c5 + bb[5], c6 + bb[6], c7 + bb[7]);
        st_half4(out + (size_t)row * 128 + ca, o1);
        st_half4(out + (size_t)row * 128 + cb, o2);
    }
}

// ---------------- fused attention: plain-exp softmax, 4-edge ILP -------------
__device__ __forceinline__ float gelu_tanh(float v) {
    float v3 = v * v * v;
    float t = tanhf(0.7978845608028654f * (v + 0.044715f * v3));
    return 0.5f * v * (1.f + t);
}

__global__ __launch_bounds__(256)
void k_attn(const float* __restrict__ att, const float* __restrict__ bias,
            float* __restrict__ dout, int layer) {
    int warp = (blockIdx.x * blockDim.x + threadIdx.x) >> 5;
    int lane = threadIdx.x & 31;
    if (warp >= Nn) return;
    const int n = warp;
    const int c4 = lane * 4;
    const unsigned full = 0xffffffffu;

    float4 xrv = ld_half4(g_xr + (size_t)n * HC + c4);
    float4 atv = *(const float4*)(att + c4);

    float s = 0.f, a0 = 0.f, a1 = 0.f, a2 = 0.f, a3 = 0.f;

    const int start = g_rowptr[n];
    const int cnt = g_deg[n];

    auto process = [&](float4 cur) {
        float z0 = cur.x + xrv.x, z1 = cur.y + xrv.y;
        float z2 = cur.z + xrv.z, z3 = cur.w + xrv.w;
        float l0 = (z0 > 0.f) ? z0 : 0.2f * z0;
        float l1 = (z1 > 0.f) ? z1 : 0.2f * z1;
        float l2 = (z2 > 0.f) ? z2 : 0.2f * z2;
        float l3 = (z3 > 0.f) ? z3 : 0.2f * z3;
        float p = l0 * atv.x + l1 * atv.y + l2 * atv.z + l3 * atv.w;
        p += __shfl_xor_sync(full, p, 1);
        p += __shfl_xor_sync(full, p, 2);
        p += __shfl_xor_sync(full, p, 4);
        p += __shfl_xor_sync(full, p, 8);
        float c = __expf(p);
        s += c;
        a0 += c * cur.x; a1 += c * cur.y;
        a2 += c * cur.z; a3 += c * cur.w;
    };

    // self loop
    process(ld_half4(g_xl + (size_t)n * HC + c4));

    for (int base = 0; base < cnt; base += 32) {
        int mm = cnt - base; if (mm > 32) mm = 32;
        // batched, coalesced src-index load; per-edge broadcast via shfl
        int sidx = g_colsrc[start + base + ((lane < mm) ? lane : 0)];
        int e = 0;
        for (; e + 3 < mm; e += 4) {
            int s0 = __shfl_sync(full, sidx, e);
            int s1 = __shfl_sync(full, sidx, e + 1);
            int s2 = __shfl_sync(full, sidx, e + 2);
            int s3 = __shfl_sync(full, sidx, e + 3);
            float4 r0 = ld_half4(g_xl + (size_t)s0 * HC + c4);
            float4 r1 = ld_half4(g_xl + (size_t)s1 * HC + c4);
            float4 r2 = ld_half4(g_xl + (size_t)s2 * HC + c4);
            float4 r3 = ld_half4(g_xl + (size_t)s3 * HC + c4);
            process(r0);
            process(r1);
            process(r2);
            process(r3);
        }
        for (; e < mm; e++) {
            int s0 = __shfl_sync(full, sidx, e);
            process(ld_half4(g_xl + (size_t)s0 * HC + c4));
        }
    }

    float inv = 1.f / s;
    float r0 = a0 * inv, r1 = a1 * inv, r2 = a2 * inv, r3 = a3 * inv;
    // combine heads: lane l (<16) pairs with lane l+16 (same channel, other head)
    float o0 = r0 + __shfl_xor_sync(full, r0, 16);
    float o1 = r1 + __shfl_xor_sync(full, r1, 16);
    float o2 = r2 + __shfl_xor_sync(full, r2, 16);
    float o3 = r3 + __shfl_xor_sync(full, r3, 16);

    if (lane < 16) {
        float4 bv = *(const float4*)(bias + c4);
        float y0 = 0.5f * o0 + bv.x;
        float y1 = 0.5f * o1 + bv.y;
        float y2 = 0.5f * o2 + bv.z;
        float y3 = 0.5f * o3 + bv.w;
        if (layer == 0) {
            y0 = gelu_tanh(y0); y1 = gelu_tanh(y1);
            y2 = gelu_tanh(y2); y3 = gelu_tanh(y3);
            *(float4*)(g_x + (size_t)n * Dd + c4) = make_float4(y0, y1, y2, y3);
        } else {
            *(float4*)(dout + (size_t)n * Dd + c4) = make_float4(y0, y1, y2, y3);
        }
    }
}

// ---------------- launcher ---------------------------------------------------
extern "C" void kernel_launch(void* const* d_in, const int* in_sizes, int n_in,
                              void* d_out, int out_size) {
    const float* x     = (const float*)d_in[0];
    const void*  edges = d_in[1];
    const float* Wl    = (const float*)d_in[2];
    const float* bl    = (const float*)d_in[3];
    const float* Wr    = (const float*)d_in[4];
    const float* br    = (const float*)d_in[5];
    const float* att   = (const float*)d_in[6];
    const float* bias  = (const float*)d_in[7];
    float* out = (float*)d_out;

    static int smem_set = 0;
    int gemm_smem = (64 * AP + 64 * 128) * (int)sizeof(float);  // 66560 B
    if (!smem_set) {
        cudaFuncSetAttribute(k_gemm, cudaFuncAttributeMaxDynamicSharedMemorySize, gemm_smem);
        smem_set = 1;
    }

    dim3 ggrid((Nn + 127) / 128, 2);
    int agrid = (Nn + 7) / 8;   // one warp per node, 8 warps/block

    k_detect  <<<1, 32>>>(edges);
    k_zero_deg<<<(Nn + 511) / 512, 512>>>();
    k_count   <<<(Ee + 255) / 256, 256>>>(edges);
    k_gemm    <<<ggrid, 256, gemm_smem>>>(x, 0, Wl, Wr, bl, br);   // layer 0 GEMM
    k_scan1   <<<NSCAN_BLOCKS, SCB>>>();
    k_scan2   <<<1, 32>>>(NSCAN_BLOCKS);
    k_scan3   <<<NSCAN_BLOCKS, SCB>>>();
    k_scatter <<<(Ee + 255) / 256, 256>>>(edges);

    k_attn<<<agrid, 256>>>(att, bias, out, 0);                      // layer 0 attn
    k_gemm<<<ggrid, 256, gemm_smem>>>(x, 1, Wl + 64 * 128, Wr + 64 * 128,
                                      bl + 128, br + 128);          // layer 1 GEMM
    k_attn<<<agrid, 256>>>(att + 128, bias + 64, out, 1);           // layer 1 attn
}